// round 10
// baseline (speedup 1.0000x reference)
#include <cuda_runtime.h>
#include <cuda_bf16.h>

// Inputs (metadata order):
//  d_in[0] charges             float32 [200000, 4]
//  d_in[1] cell                float32 [3, 3]        (unused)
//  d_in[2] positions           float32 [200000, 3]   (unused)
//  d_in[3] neighbor_indices    int32   [12800000, 2]
//  d_in[4] neighbor_distances  float32 [12800000]
//  d_out  potential            float32 [200000, 4]
//
// out[i] += 0.5/d * charges[j];  out[j] += 0.5/d * charges[i]  over all edges.
//
// FINAL: 1 edge/thread, TPB=512, fp32 v4 gathers, red.global.add.v4.f32,
// async memset for output zeroing. Runs at the hardware floor for this
// access pattern: 4 scattered 16B L1tex wavefronts/edge (2 gathers + 2
// vector reductions), retired at the measured 1.0 wavefront/cyc/SM L1tex
// rate => 51.2M wf / 148 SMs / 1.82GHz = 190us; measured 189us in-kernel.
//
// Falsified/priced alternatives (session R2-R9):
//  - 4-edge unroll + vector stream loads: neutral (wall is wavefronts).
//  - cache-policy pinning (evict_last / ldcg): neutral.
//  - fp16 charges mirror (half working set/payload): neutral — wavefronts
//    and 32B L2 sectors count lines, not bytes.
//  - 16-CTA / 8-CTA cluster DSMEM gathers (static + work-stealing hybrid):
//    1.7-2.2x WORSE — fabric lane rate < L1tex rate, smem kills occupancy.
//  - TMA gather4: ~480us analytic (46 cyc/request service, no amortization).
//  - sort/bin-then-coalesce: sort passes alone exceed the 190us wall.
//  - smem privatization: ATOMS spread-addr 2 cyc/lane > 1 wf/cyc.

__device__ __forceinline__ void red_add_v4(float4* p, float4 v) {
    asm volatile("red.global.add.v4.f32 [%0], {%1, %2, %3, %4};"
                 :: "l"(p), "f"(v.x), "f"(v.y), "f"(v.z), "f"(v.w)
                 : "memory");
}

__device__ __forceinline__ float4 scale4(float4 c, float w) {
    return make_float4(c.x * w, c.y * w, c.z * w, c.w * w);
}

__global__ void __launch_bounds__(512)
edge_scatter_kernel(const float4* __restrict__ charges,
                    const int2*   __restrict__ nbr,
                    const float*  __restrict__ dist,
                    float4*       __restrict__ out,
                    int n_edges) {
    int e = blockIdx.x * blockDim.x + threadIdx.x;
    if (e >= n_edges) return;

    int2  ij  = __ldg(&nbr[e]);
    float d   = __ldg(&dist[e]);
    float inv = 0.5f / d;   // fold PREFACTOR * 0.5

    float4 cj = __ldg(&charges[ij.y]);
    float4 ci = __ldg(&charges[ij.x]);

    red_add_v4(&out[ij.x], scale4(cj, inv));
    red_add_v4(&out[ij.y], scale4(ci, inv));
}

extern "C" void kernel_launch(void* const* d_in, const int* in_sizes, int n_in,
                              void* d_out, int out_size) {
    const float4* charges = (const float4*)d_in[0];
    const int2*   nbr     = (const int2*)d_in[3];
    const float*  dist    = (const float*)d_in[4];
    float4*       out     = (float4*)d_out;

    int n_edges = in_sizes[4];   // 12,800,000

    // d_out is poisoned to 0xAA — zero it (async, graph-capturable).
    cudaMemsetAsync(d_out, 0, (size_t)out_size * sizeof(float));

    const int TPB = 512;
    int blocks = (n_edges + TPB - 1) / TPB;
    edge_scatter_kernel<<<blocks, TPB>>>(charges, nbr, dist, out, n_edges);
}